// round 11
// baseline (speedup 1.0000x reference)
#include <cuda_runtime.h>
#include <math.h>

// NTXentLoss: B=2048, P=16, N=128, D=512 (fp32).
// R10: duty-cycle + occupancy attack (back to plain LDG streaming after the
//      cp.async.bulk experiment regressed).
//   - per-row reduce shortened: 2 shuffle levels only (4 SHFL, ~60cyc), 8
//     partials/row stored to SMEM; full row sums deferred to epilogue
//   - __launch_bounds__(256,6): 6 blocks/SM = 48 warps (75% occ)
//   - valid-only rows + positive row, fused mean

#define DDIM 512
#define D4 (DDIM / 4)
#define THREADS 256
#define NWARPS (THREADS / 32)   // 8
#define TEMP_INV 10.0f
#define COS_EPS 1e-8f

// scratch (no cudaMalloc allowed)
__device__ float g_loss[4096];
__device__ unsigned int g_count = 0;

__device__ __forceinline__ float warpReduceSum(float v) {
#pragma unroll
    for (int o = 16; o; o >>= 1) v += __shfl_down_sync(0xffffffffu, v, o);
    return v;
}

__device__ __forceinline__ float warpReduceMax(float v) {
#pragma unroll
    for (int o = 16; o; o >>= 1) v = fmaxf(v, __shfl_down_sync(0xffffffffu, v, o));
    return v;
}

__device__ __forceinline__ float blockReduceSum(float v, float* sbuf) {
    int lane = threadIdx.x & 31, wid = threadIdx.x >> 5;
    v = warpReduceSum(v);
    if (lane == 0) sbuf[wid] = v;
    __syncthreads();
    v = (threadIdx.x < NWARPS) ? sbuf[threadIdx.x] : 0.0f;
    if (wid == 0) {
#pragma unroll
        for (int o = NWARPS / 2; o; o >>= 1) v += __shfl_down_sync(0xffffffffu, v, o);
    }
    return v;
}

__device__ __forceinline__ float blockReduceMax(float v, float* sbuf) {
    int lane = threadIdx.x & 31, wid = threadIdx.x >> 5;
    v = warpReduceMax(v);
    if (lane == 0) sbuf[wid] = v;
    __syncthreads();
    v = (threadIdx.x < NWARPS) ? sbuf[threadIdx.x] : -INFINITY;
    if (wid == 0) {
#pragma unroll
        for (int o = NWARPS / 2; o; o >>= 1) v = fmaxf(v, __shfl_down_sync(0xffffffffu, v, o));
    }
    return v;
}

__global__ void __launch_bounds__(THREADS, 6)
ntxent_main_kernel(const float* __restrict__ target,
                   const float* __restrict__ positives,
                   const float* __restrict__ negatives,
                   const int* __restrict__ pos_idx,
                   const int* __restrict__ neg_mask,
                   float* __restrict__ out,
                   int B, int P, int N) {
    const int b = blockIdx.x;
    const int tid = threadIdx.x;
    const int lane = tid & 31;
    const int w = tid >> 5;

    __shared__ float4 s_tgt[D4];          // 2KB target row
    __shared__ float s_pdot[130][9];      // 8 partial dots per row (padded)
    __shared__ float s_pq[130][9];        // 8 partial sq-norms per row
    __shared__ int   s_valid[132];
    __shared__ int   s_wcnt[NWARPS];
    __shared__ float s_red[NWARPS];
    __shared__ float s_bcast[4];          // [0]=||t||, [1]=pos_sim, [2]=max
    __shared__ int   s_islast;

    // --- compact valid negative indices (deterministic prefix via ballot) ---
    int mvalid = 0;
    if (tid < N) mvalid = (neg_mask[(size_t)b * N + tid] != 0);
    unsigned bal = __ballot_sync(0xffffffffu, mvalid);
    if (lane == 0) s_wcnt[w] = __popc(bal);

    // --- target row -> SMEM; |t|^2 partial in a register ---
    float tq = 0.0f;
    if (tid < D4) {
        float4 tv = ((const float4*)(target + (size_t)b * DDIM))[tid];
        s_tgt[tid] = tv;
        tq = tv.x * tv.x + tv.y * tv.y + tv.z * tv.z + tv.w * tv.w;
    }
    const int pi = pos_idx[b];
    __syncthreads();   // s_tgt + s_wcnt ready

    int off = 0, M = 0;
#pragma unroll
    for (int j = 0; j < NWARPS; j++) {
        int c = s_wcnt[j];
        if (j < w) off += c;
        M += c;
    }
    if (mvalid) s_valid[off + __popc(bal & ((1u << lane) - 1u))] = tid;
    __syncthreads();   // s_valid ready

    // --- stream rows: valid negatives + positive as row M ---
    const float4* negb = (const float4*)(negatives + (size_t)b * (size_t)N * DDIM);
    const float4* posr = (const float4*)(positives + ((size_t)b * P + pi) * (size_t)DDIM);
    const int R = M + 1;

    for (int i = w; i < R; i += NWARPS) {
        const float4* v = (i < M) ? (negb + (size_t)s_valid[i] * D4) : posr;
        float dot = 0.0f, q = 0.0f;
#pragma unroll
        for (int k = 0; k < 4; k++) {    // 4 front-batched LDG.128
            float4 x = v[lane + 32 * k];
            float4 t = s_tgt[lane + 32 * k];
            dot = fmaf(x.x, t.x, dot); dot = fmaf(x.y, t.y, dot);
            dot = fmaf(x.z, t.z, dot); dot = fmaf(x.w, t.w, dot);
            q = fmaf(x.x, x.x, q); q = fmaf(x.y, x.y, q);
            q = fmaf(x.z, x.z, q); q = fmaf(x.w, x.w, q);
        }
        // SHORT reduce: 2 levels only -> lanes 0,4,8,... hold 4-lane sums
        dot += __shfl_down_sync(0xffffffffu, dot, 1);
        q   += __shfl_down_sync(0xffffffffu, q, 1);
        dot += __shfl_down_sync(0xffffffffu, dot, 2);
        q   += __shfl_down_sync(0xffffffffu, q, 2);
        if ((lane & 3) == 0) {
            s_pdot[i][lane >> 2] = dot;
            s_pq[i][lane >> 2] = q;
        }
    }
    __syncthreads();

    // --- epilogue: ||t||, per-row sums, LSE ---
    float tsum = blockReduceSum(tq, s_red);
    if (tid == 0) s_bcast[0] = sqrtf(tsum);
    __syncthreads();
    const float tnorm = s_bcast[0];

    float x = -INFINITY;
    if (tid < R) {
        float dot = 0.0f, q = 0.0f;
#pragma unroll
        for (int j = 0; j < 8; j++) {
            dot += s_pdot[tid][j];
            q += s_pq[tid][j];
        }
        float sim = (dot / fmaxf(sqrtf(q) * tnorm, COS_EPS)) * TEMP_INV;
        if (tid < M) x = sim;
        else s_bcast[1] = sim;   // tid == M: positive logit
    }
    __syncthreads();
    const float pos_sim = s_bcast[1];

    float m = blockReduceMax(fmaxf(x, pos_sim), s_red);
    if (tid == 0) s_bcast[2] = m;
    __syncthreads();
    m = s_bcast[2];
    float e = (x == -INFINITY) ? 0.0f : expf(x - m);
    if (tid == 0) e += expf(pos_sim - m);   // fold positive term
    __syncthreads();  // protect s_red reuse
    float S = blockReduceSum(e, s_red);

    // --- publish per-anchor loss; last finisher reduces the mean ---
    if (tid == 0) {
        g_loss[b] = logf(S) + m - pos_sim;
        __threadfence();
        unsigned int old = atomicAdd(&g_count, 1u);
        s_islast = (old == (unsigned int)(B - 1));
    }
    __syncthreads();
    if (s_islast) {
        __threadfence();
        float v = 0.0f;
        for (int k = tid; k < B; k += THREADS) v += g_loss[k];
        __syncthreads();  // s_red safe to reuse
        v = blockReduceSum(v, s_red);
        if (tid == 0) {
            out[0] = v / (float)B;
            g_count = 0;  // reset for next graph replay
        }
    }
}

extern "C" void kernel_launch(void* const* d_in, const int* in_sizes, int n_in,
                              void* d_out, int out_size) {
    const float* target = (const float*)d_in[0];
    const float* positives = (const float*)d_in[1];
    const float* negatives = (const float*)d_in[2];
    const int* pos_idx = (const int*)d_in[3];
    const int* neg_mask = (const int*)d_in[4];
    float* out = (float*)d_out;

    const int B = in_sizes[0] / DDIM;                 // 2048
    const int P = in_sizes[1] / in_sizes[0];          // 16
    const int N = in_sizes[2] / in_sizes[0];          // 128

    ntxent_main_kernel<<<B, THREADS>>>(target, positives, negatives, pos_idx,
                                       neg_mask, out, B, P, N);
}

// round 12
// speedup vs baseline: 1.1172x; 1.1172x over previous
#include <cuda_runtime.h>
#include <math.h>

// NTXentLoss: B=2048, P=16, N=128, D=512 (fp32).
// R12: R8 software-pipelined prefetch (proven +issue) COMBINED with a short
//      1-level shuffle reduce (2 SHFL instead of 10; 16 partials/row -> SMEM,
//      row sums in epilogue). 6 blocks/SM via launch_bounds. Valid-only rows,
//      positive folded as row M, fused mean.

#define DDIM 512
#define D4 (DDIM / 4)
#define THREADS 256
#define NWARPS (THREADS / 32)   // 8
#define TEMP_INV 10.0f
#define COS_EPS 1e-8f

// scratch (no cudaMalloc allowed)
__device__ float g_loss[4096];
__device__ unsigned int g_count = 0;

__device__ __forceinline__ float warpReduceSum(float v) {
#pragma unroll
    for (int o = 16; o; o >>= 1) v += __shfl_down_sync(0xffffffffu, v, o);
    return v;
}

__device__ __forceinline__ float warpReduceMax(float v) {
#pragma unroll
    for (int o = 16; o; o >>= 1) v = fmaxf(v, __shfl_down_sync(0xffffffffu, v, o));
    return v;
}

__device__ __forceinline__ float blockReduceSum(float v, float* sbuf) {
    int lane = threadIdx.x & 31, wid = threadIdx.x >> 5;
    v = warpReduceSum(v);
    if (lane == 0) sbuf[wid] = v;
    __syncthreads();
    v = (threadIdx.x < NWARPS) ? sbuf[threadIdx.x] : 0.0f;
    if (wid == 0) {
#pragma unroll
        for (int o = NWARPS / 2; o; o >>= 1) v += __shfl_down_sync(0xffffffffu, v, o);
    }
    return v;
}

__device__ __forceinline__ float blockReduceMax(float v, float* sbuf) {
    int lane = threadIdx.x & 31, wid = threadIdx.x >> 5;
    v = warpReduceMax(v);
    if (lane == 0) sbuf[wid] = v;
    __syncthreads();
    v = (threadIdx.x < NWARPS) ? sbuf[threadIdx.x] : -INFINITY;
    if (wid == 0) {
#pragma unroll
        for (int o = NWARPS / 2; o; o >>= 1) v = fmaxf(v, __shfl_down_sync(0xffffffffu, v, o));
    }
    return v;
}

__global__ void __launch_bounds__(THREADS, 6)
ntxent_main_kernel(const float* __restrict__ target,
                   const float* __restrict__ positives,
                   const float* __restrict__ negatives,
                   const int* __restrict__ pos_idx,
                   const int* __restrict__ neg_mask,
                   float* __restrict__ out,
                   int B, int P, int N) {
    const int b = blockIdx.x;
    const int tid = threadIdx.x;
    const int lane = tid & 31;
    const int w = tid >> 5;

    __shared__ float4 s_tgt[D4];          // 2KB target row
    __shared__ float s_pd[130][17];       // 16 partial dots/row, pad 17 (bank-free)
    __shared__ float s_pq[130][17];       // 16 partial sq-norms/row
    __shared__ int   s_valid[132];
    __shared__ int   s_wcnt[NWARPS];
    __shared__ float s_red[NWARPS];
    __shared__ float s_bcast[4];          // [0]=||t||, [1]=pos_sim, [2]=max
    __shared__ int   s_islast;

    // --- compact valid negative indices (deterministic prefix via ballot) ---
    int mvalid = 0;
    if (tid < N) mvalid = (neg_mask[(size_t)b * N + tid] != 0);
    unsigned bal = __ballot_sync(0xffffffffu, mvalid);
    if (lane == 0) s_wcnt[w] = __popc(bal);

    // --- target row -> SMEM; |t|^2 partial in a register ---
    float tq = 0.0f;
    if (tid < D4) {
        float4 tv = ((const float4*)(target + (size_t)b * DDIM))[tid];
        s_tgt[tid] = tv;
        tq = tv.x * tv.x + tv.y * tv.y + tv.z * tv.z + tv.w * tv.w;
    }
    const int pi = pos_idx[b];
    __syncthreads();   // s_tgt + s_wcnt ready

    int off = 0, M = 0;
#pragma unroll
    for (int j = 0; j < NWARPS; j++) {
        int c = s_wcnt[j];
        if (j < w) off += c;
        M += c;
    }
    if (mvalid) s_valid[off + __popc(bal & ((1u << lane) - 1u))] = tid;
    __syncthreads();   // s_valid ready

    // --- software-pipelined row streaming: valid negatives + positive (row M) ---
    const float4* negb = (const float4*)(negatives + (size_t)b * (size_t)N * DDIM);
    const float4* posr = (const float4*)(positives + ((size_t)b * P + pi) * (size_t)DDIM);
    const int R = M + 1;

    int i = w;
    if (i < R) {
        const float4* vc = (i < M) ? (negb + (size_t)s_valid[i] * D4) : posr;
        float4 cur[4];
#pragma unroll
        for (int k = 0; k < 4; k++) cur[k] = vc[lane + 32 * k];

        for (; i < R; i += NWARPS) {
            // prefetch NEXT row before current row's compute/reduce
            const int j = i + NWARPS;
            const float4* vn = (j < R) ? ((j < M) ? (negb + (size_t)s_valid[j] * D4) : posr)
                                       : vc;
            float4 nxt[4];
#pragma unroll
            for (int k = 0; k < 4; k++) nxt[k] = vn[lane + 32 * k];

            float dot = 0.0f, q = 0.0f;
#pragma unroll
            for (int k = 0; k < 4; k++) {
                float4 t = s_tgt[lane + 32 * k];
                dot = fmaf(cur[k].x, t.x, dot); dot = fmaf(cur[k].y, t.y, dot);
                dot = fmaf(cur[k].z, t.z, dot); dot = fmaf(cur[k].w, t.w, dot);
                q = fmaf(cur[k].x, cur[k].x, q); q = fmaf(cur[k].y, cur[k].y, q);
                q = fmaf(cur[k].z, cur[k].z, q); q = fmaf(cur[k].w, cur[k].w, q);
            }
            // SHORT reduce: 1 level (lane, lane+16) -> 16 partials per row
            dot += __shfl_down_sync(0xffffffffu, dot, 16);
            q   += __shfl_down_sync(0xffffffffu, q, 16);
            if (lane < 16) {
                s_pd[i][lane] = dot;
                s_pq[i][lane] = q;
            }

#pragma unroll
            for (int k = 0; k < 4; k++) cur[k] = nxt[k];
            vc = vn;
        }
    }
    __syncthreads();

    // --- epilogue: ||t||, per-row sums (conflict-free LDS), LSE ---
    float tsum = blockReduceSum(tq, s_red);
    if (tid == 0) s_bcast[0] = sqrtf(tsum);
    __syncthreads();
    const float tnorm = s_bcast[0];

    float x = -INFINITY;
    if (tid < R) {
        float d0 = 0.0f, d1 = 0.0f, q0 = 0.0f, q1 = 0.0f;
#pragma unroll
        for (int j = 0; j < 16; j += 2) {     // 2 accumulators: halve dep chain
            d0 += s_pd[tid][j];  d1 += s_pd[tid][j + 1];
            q0 += s_pq[tid][j];  q1 += s_pq[tid][j + 1];
        }
        float dot = d0 + d1, q = q0 + q1;
        float sim = (dot / fmaxf(sqrtf(q) * tnorm, COS_EPS)) * TEMP_INV;
        if (tid < M) x = sim;
        else s_bcast[1] = sim;   // tid == M: positive logit
    }
    __syncthreads();
    const float pos_sim = s_bcast[1];

    float m = blockReduceMax(fmaxf(x, pos_sim), s_red);
    if (tid == 0) s_bcast[2] = m;
    __syncthreads();
    m = s_bcast[2];
    float e = (x == -INFINITY) ? 0.0f : expf(x - m);
    if (tid == 0) e += expf(pos_sim - m);   // fold positive term
    __syncthreads();  // protect s_red reuse
    float S = blockReduceSum(e, s_red);

    // --- publish per-anchor loss; last finisher reduces the mean ---
    if (tid == 0) {
        g_loss[b] = logf(S) + m - pos_sim;
        __threadfence();
        unsigned int old = atomicAdd(&g_count, 1u);
        s_islast = (old == (unsigned int)(B - 1));
    }
    __syncthreads();
    if (s_islast) {
        __threadfence();
        float v = 0.0f;
        for (int k = tid; k < B; k += THREADS) v += g_loss[k];
        __syncthreads();  // s_red safe to reuse
        v = blockReduceSum(v, s_red);
        if (tid == 0) {
            out[0] = v / (float)B;
            g_count = 0;  // reset for next graph replay
        }
    }
}

extern "C" void kernel_launch(void* const* d_in, const int* in_sizes, int n_in,
                              void* d_out, int out_size) {
    const float* target = (const float*)d_in[0];
    const float* positives = (const float*)d_in[1];
    const float* negatives = (const float*)d_in[2];
    const int* pos_idx = (const int*)d_in[3];
    const int* neg_mask = (const int*)d_in[4];
    float* out = (float*)d_out;

    const int B = in_sizes[0] / DDIM;                 // 2048
    const int P = in_sizes[1] / in_sizes[0];          // 16
    const int N = in_sizes[2] / in_sizes[0];          // 128

    ntxent_main_kernel<<<B, THREADS>>>(target, positives, negatives, pos_idx,
                                       neg_mask, out, B, P, N);
}

// round 13
// speedup vs baseline: 1.3222x; 1.1835x over previous
#include <cuda_runtime.h>
#include <math.h>

// NTXentLoss: B=2048, P=16, N=128, D=512 (fp32).
// R13: R8 streaming loop (proven best) + SINGLE-WARP epilogue.
//   Block-wide epilogue (3 block reductions, ~6 barriers) replaced by one
//   __syncthreads + warp 0 doing ||t||, sims, LSE with warp shuffles only.
//   Cuts per-block serialized overhead, which R3-vs-R8 analysis shows is ~25%
//   of block lifetime under the mask (65 rows amortize it, not 129).

#define DDIM 512
#define D4 (DDIM / 4)
#define THREADS 256
#define NWARPS (THREADS / 32)   // 8
#define TEMP_INV 10.0f
#define COS_EPS 1e-8f

// scratch (no cudaMalloc allowed)
__device__ float g_loss[4096];
__device__ unsigned int g_count = 0;

__device__ __forceinline__ float warpReduceSum(float v) {
#pragma unroll
    for (int o = 16; o; o >>= 1) v += __shfl_down_sync(0xffffffffu, v, o);
    return v;
}

__device__ __forceinline__ float warpAllSum(float v) {
#pragma unroll
    for (int o = 16; o; o >>= 1) v += __shfl_xor_sync(0xffffffffu, v, o);
    return v;
}

__device__ __forceinline__ float warpAllMax(float v) {
#pragma unroll
    for (int o = 16; o; o >>= 1) v = fmaxf(v, __shfl_xor_sync(0xffffffffu, v, o));
    return v;
}

__global__ void __launch_bounds__(THREADS)
ntxent_main_kernel(const float* __restrict__ target,
                   const float* __restrict__ positives,
                   const float* __restrict__ negatives,
                   const int* __restrict__ pos_idx,
                   const int* __restrict__ neg_mask,
                   float* __restrict__ out,
                   int B, int P, int N) {
    const int b = blockIdx.x;
    const int tid = threadIdx.x;
    const int lane = tid & 31;
    const int w = tid >> 5;

    __shared__ float4 s_tgt[D4];      // 2KB target row
    __shared__ float s_dot[132];      // full row dots: [0..M-1]=negs, [M]=pos
    __shared__ float s_q[132];        // full row squared norms
    __shared__ int   s_valid[132];
    __shared__ int   s_wcnt[NWARPS];

    // --- compact valid negative indices (deterministic prefix via ballot) ---
    int mvalid = 0;
    if (tid < N) mvalid = (neg_mask[(size_t)b * N + tid] != 0);
    unsigned bal = __ballot_sync(0xffffffffu, mvalid);
    if (lane == 0) s_wcnt[w] = __popc(bal);

    // --- target row -> SMEM ---
    if (tid < D4) {
        s_tgt[tid] = ((const float4*)(target + (size_t)b * DDIM))[tid];
    }
    const int pi = pos_idx[b];
    __syncthreads();   // s_tgt + s_wcnt ready

    int off = 0, M = 0;
#pragma unroll
    for (int j = 0; j < NWARPS; j++) {
        int c = s_wcnt[j];
        if (j < w) off += c;
        M += c;
    }
    if (mvalid) s_valid[off + __popc(bal & ((1u << lane) - 1u))] = tid;
    __syncthreads();   // s_valid ready

    // --- software-pipelined row streaming (R8, unchanged) ---
    const float4* negb = (const float4*)(negatives + (size_t)b * (size_t)N * DDIM);
    const float4* posr = (const float4*)(positives + ((size_t)b * P + pi) * (size_t)DDIM);
    const int R = M + 1;

    int i = w;
    if (i < R) {
        const float4* vc = (i < M) ? (negb + (size_t)s_valid[i] * D4) : posr;
        float4 cur[4];
#pragma unroll
        for (int k = 0; k < 4; k++) cur[k] = vc[lane + 32 * k];

        for (; i < R; i += NWARPS) {
            const int j = i + NWARPS;
            const float4* vn = (j < R) ? ((j < M) ? (negb + (size_t)s_valid[j] * D4) : posr)
                                       : vc;
            float4 nxt[4];
#pragma unroll
            for (int k = 0; k < 4; k++) nxt[k] = vn[lane + 32 * k];

            float dot = 0.0f, q = 0.0f;
#pragma unroll
            for (int k = 0; k < 4; k++) {
                float4 t = s_tgt[lane + 32 * k];
                dot = fmaf(cur[k].x, t.x, dot); dot = fmaf(cur[k].y, t.y, dot);
                dot = fmaf(cur[k].z, t.z, dot); dot = fmaf(cur[k].w, t.w, dot);
                q = fmaf(cur[k].x, cur[k].x, q); q = fmaf(cur[k].y, cur[k].y, q);
                q = fmaf(cur[k].z, cur[k].z, q); q = fmaf(cur[k].w, cur[k].w, q);
            }
            dot = warpReduceSum(dot);
            q = warpReduceSum(q);
            if (lane == 0) { s_dot[i] = dot; s_q[i] = q; }

#pragma unroll
            for (int k = 0; k < 4; k++) cur[k] = nxt[k];
            vc = vn;
        }
    }
    __syncthreads();   // ONLY epilogue barrier

    // --- single-warp epilogue: warp 0 does everything; warps 1..7 exit ---
    if (w == 0) {
        // ||t||^2 from SMEM (data already resident)
        float tq = 0.0f;
#pragma unroll
        for (int k = 0; k < 4; k++) {
            float4 t = s_tgt[lane + 32 * k];
            tq = fmaf(t.x, t.x, tq); tq = fmaf(t.y, t.y, tq);
            tq = fmaf(t.z, t.z, tq); tq = fmaf(t.w, t.w, tq);
        }
        const float tnorm = sqrtf(warpAllSum(tq));

        // sims (<=5 per lane) + max; lane (M&31) captures pos_sim
        float sims[5];
        int cnt = 0;
        float mx = -INFINITY;
        float psim = -INFINITY;
        for (int r = lane; r < R; r += 32) {
            float sim = (s_dot[r] / fmaxf(sqrtf(s_q[r]) * tnorm, COS_EPS)) * TEMP_INV;
            sims[cnt++] = sim;
            mx = fmaxf(mx, sim);
            if (r == M) psim = sim;
        }
        const float pos_sim = __shfl_sync(0xffffffffu, psim, M & 31);
        mx = warpAllMax(mx);

        float e = 0.0f;
        for (int c = 0; c < cnt; c++) e += expf(sims[c] - mx);
        e = warpAllSum(e);

        // publish; last finisher (warp 0 of last block) computes the mean
        int islast = 0;
        if (lane == 0) {
            g_loss[b] = logf(e) + mx - pos_sim;
            __threadfence();
            unsigned int old = atomicAdd(&g_count, 1u);
            islast = (old == (unsigned int)(B - 1));
        }
        islast = __shfl_sync(0xffffffffu, islast, 0);
        if (islast) {
            __threadfence();
            float v = 0.0f;
            for (int k = lane; k < B; k += 32) v += g_loss[k];
            v = warpAllSum(v);
            if (lane == 0) {
                out[0] = v / (float)B;
                g_count = 0;  // reset for next graph replay
            }
        }
    }
}

extern "C" void kernel_launch(void* const* d_in, const int* in_sizes, int n_in,
                              void* d_out, int out_size) {
    const float* target = (const float*)d_in[0];
    const float* positives = (const float*)d_in[1];
    const float* negatives = (const float*)d_in[2];
    const int* pos_idx = (const int*)d_in[3];
    const int* neg_mask = (const int*)d_in[4];
    float* out = (float*)d_out;

    const int B = in_sizes[0] / DDIM;                 // 2048
    const int P = in_sizes[1] / in_sizes[0];          // 16
    const int N = in_sizes[2] / in_sizes[0];          // 128

    ntxent_main_kernel<<<B, THREADS>>>(target, positives, negatives, pos_idx,
                                       neg_mask, out, B, P, N);
}

// round 14
// speedup vs baseline: 1.3329x; 1.0081x over previous
#include <cuda_runtime.h>
#include <math.h>

// NTXentLoss: B=2048, P=16, N=128, D=512 (fp32).
// R14: R13 (single-warp epilogue, won) with register pressure fixed:
//   - two-pass epilogue over s_dot/s_q (no sims[] register array)
//   - __launch_bounds__(256,5): regs<=48 -> 5 blocks/SM (R8 residency)
//   R8 streaming loop unchanged.

#define DDIM 512
#define D4 (DDIM / 4)
#define THREADS 256
#define NWARPS (THREADS / 32)   // 8
#define TEMP_INV 10.0f
#define COS_EPS 1e-8f

// scratch (no cudaMalloc allowed)
__device__ float g_loss[4096];
__device__ unsigned int g_count = 0;

__device__ __forceinline__ float warpReduceSum(float v) {
#pragma unroll
    for (int o = 16; o; o >>= 1) v += __shfl_down_sync(0xffffffffu, v, o);
    return v;
}

__device__ __forceinline__ float warpAllSum(float v) {
#pragma unroll
    for (int o = 16; o; o >>= 1) v += __shfl_xor_sync(0xffffffffu, v, o);
    return v;
}

__device__ __forceinline__ float warpAllMax(float v) {
#pragma unroll
    for (int o = 16; o; o >>= 1) v = fmaxf(v, __shfl_xor_sync(0xffffffffu, v, o));
    return v;
}

__global__ void __launch_bounds__(THREADS, 5)
ntxent_main_kernel(const float* __restrict__ target,
                   const float* __restrict__ positives,
                   const float* __restrict__ negatives,
                   const int* __restrict__ pos_idx,
                   const int* __restrict__ neg_mask,
                   float* __restrict__ out,
                   int B, int P, int N) {
    const int b = blockIdx.x;
    const int tid = threadIdx.x;
    const int lane = tid & 31;
    const int w = tid >> 5;

    __shared__ float4 s_tgt[D4];      // 2KB target row
    __shared__ float s_dot[132];      // full row dots: [0..M-1]=negs, [M]=pos
    __shared__ float s_q[132];        // full row squared norms
    __shared__ int   s_valid[132];
    __shared__ int   s_wcnt[NWARPS];

    // --- compact valid negative indices (deterministic prefix via ballot) ---
    int mvalid = 0;
    if (tid < N) mvalid = (neg_mask[(size_t)b * N + tid] != 0);
    unsigned bal = __ballot_sync(0xffffffffu, mvalid);
    if (lane == 0) s_wcnt[w] = __popc(bal);

    // --- target row -> SMEM ---
    if (tid < D4) {
        s_tgt[tid] = ((const float4*)(target + (size_t)b * DDIM))[tid];
    }
    const int pi = pos_idx[b];
    __syncthreads();   // s_tgt + s_wcnt ready

    int off = 0, M = 0;
#pragma unroll
    for (int j = 0; j < NWARPS; j++) {
        int c = s_wcnt[j];
        if (j < w) off += c;
        M += c;
    }
    if (mvalid) s_valid[off + __popc(bal & ((1u << lane) - 1u))] = tid;
    __syncthreads();   // s_valid ready

    // --- software-pipelined row streaming (R8, unchanged) ---
    const float4* negb = (const float4*)(negatives + (size_t)b * (size_t)N * DDIM);
    const float4* posr = (const float4*)(positives + ((size_t)b * P + pi) * (size_t)DDIM);
    const int R = M + 1;

    int i = w;
    if (i < R) {
        const float4* vc = (i < M) ? (negb + (size_t)s_valid[i] * D4) : posr;
        float4 cur[4];
#pragma unroll
        for (int k = 0; k < 4; k++) cur[k] = vc[lane + 32 * k];

        for (; i < R; i += NWARPS) {
            const int j = i + NWARPS;
            const float4* vn = (j < R) ? ((j < M) ? (negb + (size_t)s_valid[j] * D4) : posr)
                                       : vc;
            float4 nxt[4];
#pragma unroll
            for (int k = 0; k < 4; k++) nxt[k] = vn[lane + 32 * k];

            float dot = 0.0f, q = 0.0f;
#pragma unroll
            for (int k = 0; k < 4; k++) {
                float4 t = s_tgt[lane + 32 * k];
                dot = fmaf(cur[k].x, t.x, dot); dot = fmaf(cur[k].y, t.y, dot);
                dot = fmaf(cur[k].z, t.z, dot); dot = fmaf(cur[k].w, t.w, dot);
                q = fmaf(cur[k].x, cur[k].x, q); q = fmaf(cur[k].y, cur[k].y, q);
                q = fmaf(cur[k].z, cur[k].z, q); q = fmaf(cur[k].w, cur[k].w, q);
            }
            dot = warpReduceSum(dot);
            q = warpReduceSum(q);
            if (lane == 0) { s_dot[i] = dot; s_q[i] = q; }

#pragma unroll
            for (int k = 0; k < 4; k++) cur[k] = nxt[k];
            vc = vn;
        }
    }
    __syncthreads();   // ONLY epilogue barrier

    // --- single-warp epilogue (two-pass, no register array) ---
    if (w == 0) {
        // ||t||^2 from SMEM (resident)
        float tq = 0.0f;
#pragma unroll
        for (int k = 0; k < 4; k++) {
            float4 t = s_tgt[lane + 32 * k];
            tq = fmaf(t.x, t.x, tq); tq = fmaf(t.y, t.y, tq);
            tq = fmaf(t.z, t.z, tq); tq = fmaf(t.w, t.w, tq);
        }
        const float tnorm = sqrtf(warpAllSum(tq));

        // convert rows to logits in place: s_dot[r] <- sim(r)
        float mx = -INFINITY;
        for (int r = lane; r < R; r += 32) {
            float sim = (s_dot[r] / fmaxf(sqrtf(s_q[r]) * tnorm, COS_EPS)) * TEMP_INV;
            s_dot[r] = sim;
            mx = fmaxf(mx, sim);
        }
        __syncwarp();
        mx = warpAllMax(mx);

        float e = 0.0f;
        for (int r = lane; r < R; r += 32) e += expf(s_dot[r] - mx);
        e = warpAllSum(e);
        const float pos_sim = s_dot[M];   // uniform SMEM read, all lanes

        // publish; last finisher computes the mean
        int islast = 0;
        if (lane == 0) {
            g_loss[b] = logf(e) + mx - pos_sim;
            __threadfence();
            unsigned int old = atomicAdd(&g_count, 1u);
            islast = (old == (unsigned int)(B - 1));
        }
        islast = __shfl_sync(0xffffffffu, islast, 0);
        if (islast) {
            __threadfence();
            float v = 0.0f;
            for (int k = lane; k < B; k += 32) v += g_loss[k];
            v = warpAllSum(v);
            if (lane == 0) {
                out[0] = v / (float)B;
                g_count = 0;  // reset for next graph replay
            }
        }
    }
}

extern "C" void kernel_launch(void* const* d_in, const int* in_sizes, int n_in,
                              void* d_out, int out_size) {
    const float* target = (const float*)d_in[0];
    const float* positives = (const float*)d_in[1];
    const float* negatives = (const float*)d_in[2];
    const int* pos_idx = (const int*)d_in[3];
    const int* neg_mask = (const int*)d_in[4];
    float* out = (float*)d_out;

    const int B = in_sizes[0] / DDIM;                 // 2048
    const int P = in_sizes[1] / in_sizes[0];          // 16
    const int N = in_sizes[2] / in_sizes[0];          // 128

    ntxent_main_kernel<<<B, THREADS>>>(target, positives, negatives, pos_idx,
                                       neg_mask, out, B, P, N);
}